// round 1
// baseline (speedup 1.0000x reference)
#include <cuda_runtime.h>
#include <math.h>

#define NTOK 4096
#define CDIM 768
#define NH   12
#define HD   64
#define FF   3072
#define QKVD 2304

// ---------------- scratch (static device globals; no allocs allowed) --------
__device__ float g_h[NTOK * CDIM];       // LN output / reused
__device__ float g_qkv[NTOK * QKVD];     // qkv
__device__ float g_o[NTOK * CDIM];       // attention output
__device__ float g_x1[NTOK * CDIM];      // x + attn proj
__device__ float g_fc1[NTOK * FF];       // fc1+gelu output

// ---------------- LayerNorm: one block per row (768 = 256*3) ----------------
__global__ __launch_bounds__(256) void ln_kernel(
    const float* __restrict__ x, const float* __restrict__ g,
    const float* __restrict__ b, float* __restrict__ out)
{
    const int row = blockIdx.x;
    const int tid = threadIdx.x;
    const float* xr = x + row * CDIM;
    float v[3];
    float s = 0.f;
#pragma unroll
    for (int i = 0; i < 3; i++) { v[i] = xr[tid + 256 * i]; s += v[i]; }

    __shared__ float sh[8];
    // reduce sum
#pragma unroll
    for (int o = 16; o > 0; o >>= 1) s += __shfl_xor_sync(0xffffffffu, s, o);
    if ((tid & 31) == 0) sh[tid >> 5] = s;
    __syncthreads();
    if (tid < 8) {
        s = sh[tid];
#pragma unroll
        for (int o = 4; o > 0; o >>= 1) s += __shfl_xor_sync(0xffu, s, o);
        if (tid == 0) sh[0] = s;
    }
    __syncthreads();
    const float mu = sh[0] * (1.0f / CDIM);
    __syncthreads();

    float s2 = 0.f;
#pragma unroll
    for (int i = 0; i < 3; i++) { float d = v[i] - mu; s2 += d * d; }
#pragma unroll
    for (int o = 16; o > 0; o >>= 1) s2 += __shfl_xor_sync(0xffffffffu, s2, o);
    if ((tid & 31) == 0) sh[tid >> 5] = s2;
    __syncthreads();
    if (tid < 8) {
        s2 = sh[tid];
#pragma unroll
        for (int o = 4; o > 0; o >>= 1) s2 += __shfl_xor_sync(0xffu, s2, o);
        if (tid == 0) sh[0] = s2;
    }
    __syncthreads();
    const float rstd = rsqrtf(sh[0] * (1.0f / CDIM) + 1e-5f);

    float* orow = out + row * CDIM;
#pragma unroll
    for (int i = 0; i < 3; i++) {
        int c = tid + 256 * i;
        orow[c] = (v[i] - mu) * rstd * g[c] + b[c];
    }
}

// ---------------- tiled SGEMM-NT: C[M,N] = A[M,K] * B[N,K]^T (+epilogue) ----
// BM=BN=64, BK=16, 256 threads, 4x4 per-thread microtile.
template <bool HAS_BIAS, bool HAS_RES, bool DO_GELU>
__global__ __launch_bounds__(256) void gemm_nt_kernel(
    const float* __restrict__ A, const float* __restrict__ B,
    const float* __restrict__ bias, const float* __restrict__ res,
    float* __restrict__ C, int M, int Nc, int K)
{
    __shared__ float As[16][64];
    __shared__ float Bs[16][64];

    const int tid = threadIdx.x;
    const int tx = tid & 15;          // 0..15 -> N
    const int ty = tid >> 4;          // 0..15 -> M
    const int m0 = blockIdx.y * 64;
    const int n0 = blockIdx.x * 64;

    const int lr = tid >> 2;          // 0..63
    const int lc = (tid & 3) * 4;     // 0,4,8,12

    float acc[4][4];
#pragma unroll
    for (int i = 0; i < 4; i++)
#pragma unroll
        for (int j = 0; j < 4; j++) acc[i][j] = 0.f;

    const int ktiles = K >> 4;
    const float* aPtr = A + (m0 + lr) * (long)K + lc;
    const float* bPtr = B + (n0 + lr) * (long)K + lc;

    for (int kt = 0; kt < ktiles; kt++) {
        float4 av = *(const float4*)(aPtr + kt * 16);
        float4 bv = *(const float4*)(bPtr + kt * 16);
        As[lc + 0][lr] = av.x; As[lc + 1][lr] = av.y;
        As[lc + 2][lr] = av.z; As[lc + 3][lr] = av.w;
        Bs[lc + 0][lr] = bv.x; Bs[lc + 1][lr] = bv.y;
        Bs[lc + 2][lr] = bv.z; Bs[lc + 3][lr] = bv.w;
        __syncthreads();
#pragma unroll
        for (int kk = 0; kk < 16; kk++) {
            float4 a = *(const float4*)&As[kk][ty * 4];
            float4 b = *(const float4*)&Bs[kk][tx * 4];
            float ar[4] = {a.x, a.y, a.z, a.w};
            float br[4] = {b.x, b.y, b.z, b.w};
#pragma unroll
            for (int i = 0; i < 4; i++)
#pragma unroll
                for (int j = 0; j < 4; j++) acc[i][j] += ar[i] * br[j];
        }
        __syncthreads();
    }

#pragma unroll
    for (int i = 0; i < 4; i++) {
        const int m = m0 + ty * 4 + i;
        float* crow = C + m * (long)Nc + n0 + tx * 4;
        const float* rrow = HAS_RES ? (res + m * (long)Nc + n0 + tx * 4) : nullptr;
        float4 v;
        float vv[4];
#pragma unroll
        for (int j = 0; j < 4; j++) {
            float t = acc[i][j];
            if (HAS_BIAS) t += bias[n0 + tx * 4 + j];
            if (DO_GELU)  t = 0.5f * t * (1.0f + erff(t * 0.70710678118654752f));
            if (HAS_RES)  t += rrow[j];
            vv[j] = t;
        }
        v.x = vv[0]; v.y = vv[1]; v.z = vv[2]; v.w = vv[3];
        *(float4*)crow = v;
    }
}

// ---------------- RoPE on q and k slices of qkv ------------------------------
__global__ __launch_bounds__(256) void rope_kernel(
    float* __restrict__ qkv, const float* __restrict__ cos_t,
    const float* __restrict__ sin_t)
{
    int idx = blockIdx.x * blockDim.x + threadIdx.x;   // (n, h, i)
    if (idx >= NTOK * NH * (HD / 2)) return;
    const int i = idx & 31;
    const int h = (idx >> 5) % NH;
    const int n = idx / (NH * (HD / 2));
    const float c = cos_t[n * 32 + i];
    const float s = sin_t[n * 32 + i];
#pragma unroll
    for (int sel = 0; sel < 2; sel++) {
        float* p = qkv + (long)n * QKVD + sel * CDIM + h * HD + 2 * i;
        float t0 = p[0], t1 = p[1];
        p[0] = t0 * c - t1 * s;
        p[1] = t0 * s + t1 * c;
    }
}

// ---------------- flash attention (fp32, online softmax) --------------------
// grid: (NTOK/128, NH). 256 threads: 128 rows x 2 half-dim threads.
__global__ __launch_bounds__(256) void attn_kernel(
    const float* __restrict__ qkv, float* __restrict__ out)
{
    __shared__ float k_s[32][64];
    __shared__ float v_s[32][64];

    const int tid = threadIdx.x;
    const int row = tid >> 1;        // 0..127
    const int half = tid & 1;        // 0/1
    const int n = blockIdx.x * 128 + row;
    const int h = blockIdx.y;
    const float scale = 0.125f;      // 1/sqrt(64)

    float q[32], O[32];
    {
        const float* qp = qkv + (long)n * QKVD + h * HD + half * 32;
#pragma unroll
        for (int d = 0; d < 32; d++) { q[d] = qp[d] * scale; O[d] = 0.f; }
    }
    float m = -1e30f, l = 0.f;

    for (int kt = 0; kt < NTOK / 32; kt++) {
        // cooperative load of K,V tile: 2*2048 floats, 8 each
        {
            const int flat = tid * 8;
            const int j = flat >> 6;
            const int c = flat & 63;
            const float* kp = qkv + (long)(kt * 32 + j) * QKVD + CDIM + h * HD + c;
            const float* vp = kp + CDIM;
            float4 k0 = *(const float4*)kp;
            float4 k1 = *(const float4*)(kp + 4);
            float4 v0 = *(const float4*)vp;
            float4 v1 = *(const float4*)(vp + 4);
            *(float4*)&k_s[j][c] = k0; *(float4*)&k_s[j][c + 4] = k1;
            *(float4*)&v_s[j][c] = v0; *(float4*)&v_s[j][c + 4] = v1;
        }
        __syncthreads();

        float p[32];
        float mt = -1e30f;
#pragma unroll
        for (int j = 0; j < 32; j++) {
            float s = 0.f;
#pragma unroll
            for (int d = 0; d < 32; d++) s += q[d] * k_s[j][half * 32 + d];
            s += __shfl_xor_sync(0xffffffffu, s, 1);
            p[j] = s;
            mt = fmaxf(mt, s);
        }
        const float mnew = fmaxf(m, mt);
        const float corr = __expf(m - mnew);
        l *= corr;
#pragma unroll
        for (int d = 0; d < 32; d++) O[d] *= corr;
#pragma unroll
        for (int j = 0; j < 32; j++) {
            const float e = __expf(p[j] - mnew);
            l += e;
#pragma unroll
            for (int d = 0; d < 32; d++) O[d] += e * v_s[j][half * 32 + d];
        }
        m = mnew;
        __syncthreads();
    }

    const float inv_l = 1.0f / l;
    float* op = out + (long)n * CDIM + h * HD + half * 32;
#pragma unroll
    for (int d = 0; d < 32; d++) op[d] = O[d] * inv_l;
}

// ---------------- launch ----------------------------------------------------
extern "C" void kernel_launch(void* const* d_in, const int* in_sizes, int n_in,
                              void* d_out, int out_size)
{
    const float* x        = (const float*)d_in[0];
    const float* cos_t    = (const float*)d_in[1];
    const float* sin_t    = (const float*)d_in[2];
    const float* w_qkv    = (const float*)d_in[3];
    const float* w_proj   = (const float*)d_in[4];
    const float* b_proj   = (const float*)d_in[5];
    const float* g1       = (const float*)d_in[6];
    const float* beta1    = (const float*)d_in[7];
    const float* g2       = (const float*)d_in[8];
    const float* beta2    = (const float*)d_in[9];
    const float* w_fc1    = (const float*)d_in[10];
    const float* b_fc1    = (const float*)d_in[11];
    const float* w_fc2    = (const float*)d_in[12];
    const float* b_fc2    = (const float*)d_in[13];
    float* out = (float*)d_out;

    float *h, *qkv, *o, *x1, *fc1;
    cudaGetSymbolAddress((void**)&h,   g_h);
    cudaGetSymbolAddress((void**)&qkv, g_qkv);
    cudaGetSymbolAddress((void**)&o,   g_o);
    cudaGetSymbolAddress((void**)&x1,  g_x1);
    cudaGetSymbolAddress((void**)&fc1, g_fc1);

    // 1. h = LN1(x)
    ln_kernel<<<NTOK, 256>>>(x, g1, beta1, h);
    // 2. qkv = h @ w_qkv^T
    gemm_nt_kernel<false, false, false><<<dim3(QKVD / 64, NTOK / 64), 256>>>(
        h, w_qkv, nullptr, nullptr, qkv, NTOK, QKVD, CDIM);
    // 3. RoPE(q, k)
    rope_kernel<<<(NTOK * NH * 32 + 255) / 256, 256>>>(qkv, cos_t, sin_t);
    // 4. o = attention(q, k, v)
    attn_kernel<<<dim3(NTOK / 128, NH), 256>>>(qkv, o);
    // 5. x1 = x + o @ w_proj^T + b_proj
    gemm_nt_kernel<true, true, false><<<dim3(CDIM / 64, NTOK / 64), 256>>>(
        o, w_proj, b_proj, x, x1, NTOK, CDIM, CDIM);
    // 6. h = LN2(x1)
    ln_kernel<<<NTOK, 256>>>(x1, g2, beta2, h);
    // 7. fc1 = gelu(h @ w_fc1^T + b_fc1)
    gemm_nt_kernel<true, false, true><<<dim3(FF / 64, NTOK / 64), 256>>>(
        h, w_fc1, b_fc1, nullptr, fc1, NTOK, FF, CDIM);
    // 8. out = x1 + fc1 @ w_fc2^T + b_fc2
    gemm_nt_kernel<true, true, false><<<dim3(CDIM / 64, NTOK / 64), 256>>>(
        fc1, w_fc2, b_fc2, x1, out, NTOK, CDIM, FF);
}

// round 3
// speedup vs baseline: 3.8272x; 3.8272x over previous
#include <cuda_runtime.h>
#include <math.h>
#include <stdint.h>

#define NTOK 4096
#define CDIM 768
#define NH   12
#define HD   64
#define FF   3072
#define QKVD 2304

// ---------------- scratch ----------------------------------------------------
__device__ float g_h[NTOK * CDIM];
__device__ float g_qkv[NTOK * QKVD];
__device__ float g_o[NTOK * CDIM];
__device__ float g_x1[NTOK * CDIM];
__device__ float g_fc1[NTOK * FF];

// ---------------- helpers ----------------------------------------------------
__device__ __forceinline__ uint32_t cvt_tf32(float f) {
    uint32_t r;
    asm("cvt.rna.tf32.f32 %0, %1;" : "=r"(r) : "f"(f));
    return r;
}

// d += a * b  (m16n8k8, tf32 inputs, f32 accum)
__device__ __forceinline__ void mma_tf32(float* d, const uint32_t* a, const uint32_t* b) {
    asm volatile(
        "mma.sync.aligned.m16n8k8.row.col.f32.tf32.tf32.f32 "
        "{%0,%1,%2,%3}, {%4,%5,%6,%7}, {%8,%9}, {%0,%1,%2,%3};\n"
        : "+f"(d[0]), "+f"(d[1]), "+f"(d[2]), "+f"(d[3])
        : "r"(a[0]), "r"(a[1]), "r"(a[2]), "r"(a[3]), "r"(b[0]), "r"(b[1]));
}

// fast exp on the FMA pipe (x <= 0 in softmax; clamp handles -1e30 sentinels)
__device__ __forceinline__ float fexp(float x) {
    x = fmaxf(x, -80.0f);
    float t = x * 1.4426950408889634f;
    int e = __float2int_rn(t);
    float f = t - (float)e;
    float p = fmaf(f, 0.00133336f, 0.00961813f);
    p = fmaf(f, p, 0.0555041f);
    p = fmaf(f, p, 0.2402265f);
    p = fmaf(f, p, 0.6931472f);
    p = fmaf(f, p, 1.0f);
    return __int_as_float((e + 127) << 23) * p;
}

// ---------------- LayerNorm --------------------------------------------------
__global__ __launch_bounds__(256) void ln_kernel(
    const float* __restrict__ x, const float* __restrict__ g,
    const float* __restrict__ b, float* __restrict__ out)
{
    const int row = blockIdx.x;
    const int tid = threadIdx.x;
    const float* xr = x + row * CDIM;
    float v[3];
    float s = 0.f;
#pragma unroll
    for (int i = 0; i < 3; i++) { v[i] = xr[tid + 256 * i]; s += v[i]; }

    __shared__ float sh[8];
#pragma unroll
    for (int o = 16; o > 0; o >>= 1) s += __shfl_xor_sync(0xffffffffu, s, o);
    if ((tid & 31) == 0) sh[tid >> 5] = s;
    __syncthreads();
    if (tid < 8) {
        s = sh[tid];
#pragma unroll
        for (int o = 4; o > 0; o >>= 1) s += __shfl_xor_sync(0xffu, s, o);
        if (tid == 0) sh[0] = s;
    }
    __syncthreads();
    const float mu = sh[0] * (1.0f / CDIM);
    __syncthreads();

    float s2 = 0.f;
#pragma unroll
    for (int i = 0; i < 3; i++) { float d = v[i] - mu; s2 += d * d; }
#pragma unroll
    for (int o = 16; o > 0; o >>= 1) s2 += __shfl_xor_sync(0xffffffffu, s2, o);
    if ((tid & 31) == 0) sh[tid >> 5] = s2;
    __syncthreads();
    if (tid < 8) {
        s2 = sh[tid];
#pragma unroll
        for (int o = 4; o > 0; o >>= 1) s2 += __shfl_xor_sync(0xffu, s2, o);
        if (tid == 0) sh[0] = s2;
    }
    __syncthreads();
    const float rstd = rsqrtf(sh[0] * (1.0f / CDIM) + 1e-5f);

    float* orow = out + row * CDIM;
#pragma unroll
    for (int i = 0; i < 3; i++) {
        int c = tid + 256 * i;
        orow[c] = (v[i] - mu) * rstd * g[c] + b[c];
    }
}

// ---------------- tf32 mma GEMM-NT: C[M,N] = A[M,K]*B[N,K]^T (+epilogue) -----
// CTA 128x128, BK=32, 8 warps (4 M x 2 N), warp tile 32x64.
// smem: 2 stages, each stage = A[128][36] + B[128][36] floats.
#define GSA 36
#define GSTAGE (2 * 128 * GSA)   // floats per stage (A+B)

template <bool HAS_BIAS, bool HAS_RES, bool DO_GELU>
__global__ __launch_bounds__(256) void gemm_mma(
    const float* __restrict__ A, const float* __restrict__ B,
    const float* __restrict__ bias, const float* __restrict__ res,
    float* __restrict__ C, int M, int Nc, int K)
{
    extern __shared__ float sm[];
    const int tid = threadIdx.x;
    const int lane = tid & 31;
    const int wid = tid >> 5;
    const int wm = (wid & 3) * 32;
    const int wn = (wid >> 2) * 64;
    const int m0 = blockIdx.y * 128;
    const int n0 = blockIdx.x * 128;
    const int r = lane >> 2;
    const int q = lane & 3;

    const int lrow = tid >> 1;
    const int lcol = (tid & 1) * 16;
    const float* Ag = A + (long)(m0 + lrow) * K + lcol;
    const float* Bg = B + (long)(n0 + lrow) * K + lcol;
    const int ktiles = K >> 5;

    float acc[2][8][4];
#pragma unroll
    for (int mt = 0; mt < 2; mt++)
#pragma unroll
        for (int nt = 0; nt < 8; nt++)
#pragma unroll
            for (int j = 0; j < 4; j++) acc[mt][nt][j] = 0.f;

    float4 ra[4], rb[4];
    // prefetch tile 0
#pragma unroll
    for (int v = 0; v < 4; v++) {
        ra[v] = *(const float4*)(Ag + v * 4);
        rb[v] = *(const float4*)(Bg + v * 4);
    }
    // sts tile 0 -> stage 0
    {
        uint32_t* Au = (uint32_t*)sm;
        uint32_t* Bu = Au + 128 * GSA;
#pragma unroll
        for (int v = 0; v < 4; v++) {
            int off = lrow * GSA + lcol + v * 4;
            uint4 at = {cvt_tf32(ra[v].x), cvt_tf32(ra[v].y), cvt_tf32(ra[v].z), cvt_tf32(ra[v].w)};
            uint4 bt = {cvt_tf32(rb[v].x), cvt_tf32(rb[v].y), cvt_tf32(rb[v].z), cvt_tf32(rb[v].w)};
            *(uint4*)(Au + off) = at;
            *(uint4*)(Bu + off) = bt;
        }
    }
    // prefetch tile 1
    if (ktiles > 1) {
#pragma unroll
        for (int v = 0; v < 4; v++) {
            ra[v] = *(const float4*)(Ag + 32 + v * 4);
            rb[v] = *(const float4*)(Bg + 32 + v * 4);
        }
    }
    __syncthreads();

    for (int kt = 0; kt < ktiles; kt++) {
        const int b = kt & 1;
        if (kt + 1 < ktiles) {
            // sts tile kt+1 -> other stage (its last readers synced at end of kt-1)
            uint32_t* Au = (uint32_t*)(sm + (b ^ 1) * GSTAGE);
            uint32_t* Bu = Au + 128 * GSA;
#pragma unroll
            for (int v = 0; v < 4; v++) {
                int off = lrow * GSA + lcol + v * 4;
                uint4 at = {cvt_tf32(ra[v].x), cvt_tf32(ra[v].y), cvt_tf32(ra[v].z), cvt_tf32(ra[v].w)};
                uint4 bt = {cvt_tf32(rb[v].x), cvt_tf32(rb[v].y), cvt_tf32(rb[v].z), cvt_tf32(rb[v].w)};
                *(uint4*)(Au + off) = at;
                *(uint4*)(Bu + off) = bt;
            }
            if (kt + 2 < ktiles) {
#pragma unroll
                for (int v = 0; v < 4; v++) {
                    ra[v] = *(const float4*)(Ag + (kt + 2) * 32 + v * 4);
                    rb[v] = *(const float4*)(Bg + (kt + 2) * 32 + v * 4);
                }
            }
        }
        // mma over stage b
        {
            const uint32_t* Au = (const uint32_t*)(sm + b * GSTAGE);
            const uint32_t* Bu = Au + 128 * GSA;
#pragma unroll
            for (int kc = 0; kc < 4; kc++) {
                uint32_t af[2][4];
#pragma unroll
                for (int mt = 0; mt < 2; mt++) {
                    const uint32_t* base = Au + (wm + mt * 16 + r) * GSA + kc * 8 + q;
                    af[mt][0] = base[0];
                    af[mt][1] = base[8 * GSA];
                    af[mt][2] = base[4];
                    af[mt][3] = base[8 * GSA + 4];
                }
#pragma unroll
                for (int nt = 0; nt < 8; nt++) {
                    uint32_t bf[2];
                    const uint32_t* base = Bu + (wn + nt * 8 + r) * GSA + kc * 8 + q;
                    bf[0] = base[0];
                    bf[1] = base[4];
#pragma unroll
                    for (int mt = 0; mt < 2; mt++)
                        mma_tf32(acc[mt][nt], af[mt], bf);
                }
            }
        }
        __syncthreads();
    }

    // epilogue: c-frag (row = lane/4 (+8), cols = 2q, 2q+1)
#pragma unroll
    for (int mt = 0; mt < 2; mt++) {
#pragma unroll
        for (int rr = 0; rr < 2; rr++) {
            const int m = m0 + wm + mt * 16 + r + rr * 8;
            float* crow = C + (long)m * Nc;
            const float* rrow = HAS_RES ? (res + (long)m * Nc) : nullptr;
#pragma unroll
            for (int nt = 0; nt < 8; nt++) {
                const int n = n0 + wn + nt * 8 + 2 * q;
                float v0 = acc[mt][nt][rr * 2 + 0];
                float v1 = acc[mt][nt][rr * 2 + 1];
                if (HAS_BIAS) { v0 += bias[n]; v1 += bias[n + 1]; }
                if (DO_GELU) {
                    v0 = 0.5f * v0 * (1.0f + erff(v0 * 0.70710678118654752f));
                    v1 = 0.5f * v1 * (1.0f + erff(v1 * 0.70710678118654752f));
                }
                if (HAS_RES) { v0 += rrow[n]; v1 += rrow[n + 1]; }
                float2 w = {v0, v1};
                *(float2*)(crow + n) = w;
            }
        }
    }
}

// ---------------- RoPE -------------------------------------------------------
__global__ __launch_bounds__(256) void rope_kernel(
    float* __restrict__ qkv, const float* __restrict__ cos_t,
    const float* __restrict__ sin_t)
{
    int idx = blockIdx.x * blockDim.x + threadIdx.x;
    if (idx >= NTOK * NH * (HD / 2)) return;
    const int i = idx & 31;
    const int h = (idx >> 5) % NH;
    const int n = idx / (NH * (HD / 2));
    const float c = cos_t[n * 32 + i];
    const float s = sin_t[n * 32 + i];
#pragma unroll
    for (int sel = 0; sel < 2; sel++) {
        float* p = qkv + (long)n * QKVD + sel * CDIM + h * HD + 2 * i;
        float t0 = p[0], t1 = p[1];
        p[0] = t0 * c - t1 * s;
        p[1] = t0 * s + t1 * c;
    }
}

// ---------------- flash attention with tf32 mma ------------------------------
// CTA: 128 q-rows x one head; 8 warps, warp = 16 q-rows. Key tiles of 64.
// smem: Ks[64][68], Vs[64][68], Qs/Ps[128][68].
__global__ __launch_bounds__(256) void attn_mma(
    const float* __restrict__ qkv, float* __restrict__ out)
{
    extern __shared__ float sm[];
    float* Ks = sm;                 // [key][d] stride 68 (tf32 bits)
    float* Vs = sm + 64 * 68;       // [key][d] stride 68 (tf32 bits)
    float* Qs = sm + 2 * 64 * 68;   // [128][68]; later: per-warp P tiles

    const int tid = threadIdx.x;
    const int lane = tid & 31;
    const int wid = tid >> 5;
    const int h = blockIdx.y;
    const int q0 = blockIdx.x * 128;
    const int r = lane >> 2;
    const int q = lane & 3;

    // stage Q (scaled, tf32)
    {
        const int row = tid >> 1;
        const int c0 = (tid & 1) * 32;
        const float* qp = qkv + (long)(q0 + row) * QKVD + h * HD + c0;
        uint32_t* dst = (uint32_t*)(Qs + row * 68 + c0);
#pragma unroll
        for (int v = 0; v < 8; v++) {
            float4 t = *(const float4*)(qp + v * 4);
            dst[v * 4 + 0] = cvt_tf32(t.x * 0.125f);
            dst[v * 4 + 1] = cvt_tf32(t.y * 0.125f);
            dst[v * 4 + 2] = cvt_tf32(t.z * 0.125f);
            dst[v * 4 + 3] = cvt_tf32(t.w * 0.125f);
        }
    }
    __syncthreads();

    // Q a-fragments (per warp: 16 rows x 64 d, 8 k-steps)
    uint32_t qf[8][4];
    {
        const uint32_t* Qu = (const uint32_t*)(Qs + wid * 16 * 68);
#pragma unroll
        for (int kc = 0; kc < 8; kc++) {
            const uint32_t* b = Qu + r * 68 + kc * 8 + q;
            qf[kc][0] = b[0];
            qf[kc][1] = b[8 * 68];
            qf[kc][2] = b[4];
            qf[kc][3] = b[8 * 68 + 4];
        }
    }
    __syncthreads();   // Qs now reusable as P

    float m0v = -1e30f, m1v = -1e30f, l0 = 0.f, l1 = 0.f;
    float of[8][4];
#pragma unroll
    for (int nt = 0; nt < 8; nt++)
#pragma unroll
        for (int j = 0; j < 4; j++) of[nt][j] = 0.f;

    uint32_t* Pu = (uint32_t*)(Qs + wid * 16 * 68);

    for (int kt = 0; kt < NTOK / 64; kt++) {
        // load K,V tile (64x64 each), tf32
        {
            const int kr = tid >> 2;
            const int c0 = (tid & 3) * 16;
            const float* kp = qkv + (long)(kt * 64 + kr) * QKVD + CDIM + h * HD + c0;
            const float* vp = kp + CDIM;
            uint32_t* kd = (uint32_t*)(Ks + kr * 68 + c0);
            uint32_t* vd = (uint32_t*)(Vs + kr * 68 + c0);
#pragma unroll
            for (int v = 0; v < 4; v++) {
                float4 kk = *(const float4*)(kp + v * 4);
                float4 vv = *(const float4*)(vp + v * 4);
                kd[v * 4 + 0] = cvt_tf32(kk.x); kd[v * 4 + 1] = cvt_tf32(kk.y);
                kd[v * 4 + 2] = cvt_tf32(kk.z); kd[v * 4 + 3] = cvt_tf32(kk.w);
                vd[v * 4 + 0] = cvt_tf32(vv.x); vd[v * 4 + 1] = cvt_tf32(vv.y);
                vd[v * 4 + 2] = cvt_tf32(vv.z); vd[v * 4 + 3] = cvt_tf32(vv.w);
            }
        }
        __syncthreads();

        // S = Q K^T : warp 16x64 tile
        float sf[8][4];
#pragma unroll
        for (int nt = 0; nt < 8; nt++)
#pragma unroll
            for (int j = 0; j < 4; j++) sf[nt][j] = 0.f;
        {
            const uint32_t* Ku = (const uint32_t*)Ks;
#pragma unroll
            for (int kc = 0; kc < 8; kc++) {
#pragma unroll
                for (int nt = 0; nt < 8; nt++) {
                    uint32_t bf[2];
                    const uint32_t* bb = Ku + (nt * 8 + r) * 68 + kc * 8 + q;
                    bf[0] = bb[0];
                    bf[1] = bb[4];
                    mma_tf32(sf[nt], qf[kc], bf);
                }
            }
        }

        // online softmax (rows r0 = r, r1 = r + 8 of the warp tile)
        float rm0 = -1e30f, rm1 = -1e30f;
#pragma unroll
        for (int nt = 0; nt < 8; nt++) {
            rm0 = fmaxf(rm0, fmaxf(sf[nt][0], sf[nt][1]));
            rm1 = fmaxf(rm1, fmaxf(sf[nt][2], sf[nt][3]));
        }
        rm0 = fmaxf(rm0, __shfl_xor_sync(0xffffffffu, rm0, 1));
        rm0 = fmaxf(rm0, __shfl_xor_sync(0xffffffffu, rm0, 2));
        rm1 = fmaxf(rm1, __shfl_xor_sync(0xffffffffu, rm1, 1));
        rm1 = fmaxf(rm1, __shfl_xor_sync(0xffffffffu, rm1, 2));
        const float mn0 = fmaxf(m0v, rm0);
        const float mn1 = fmaxf(m1v, rm1);
        const float corr0 = fexp(m0v - mn0);
        const float corr1 = fexp(m1v - mn1);
        float rs0 = 0.f, rs1 = 0.f;
#pragma unroll
        for (int nt = 0; nt < 8; nt++) {
            float p0 = fexp(sf[nt][0] - mn0);
            float p1 = fexp(sf[nt][1] - mn0);
            float p2 = fexp(sf[nt][2] - mn1);
            float p3 = fexp(sf[nt][3] - mn1);
            rs0 += p0 + p1;
            rs1 += p2 + p3;
            uint2 w0 = {cvt_tf32(p0), cvt_tf32(p1)};
            uint2 w1 = {cvt_tf32(p2), cvt_tf32(p3)};
            *(uint2*)(Pu + r * 68 + nt * 8 + 2 * q) = w0;
            *(uint2*)(Pu + (r + 8) * 68 + nt * 8 + 2 * q) = w1;
        }
        rs0 += __shfl_xor_sync(0xffffffffu, rs0, 1);
        rs0 += __shfl_xor_sync(0xffffffffu, rs0, 2);
        rs1 += __shfl_xor_sync(0xffffffffu, rs1, 1);
        rs1 += __shfl_xor_sync(0xffffffffu, rs1, 2);
        l0 = l0 * corr0 + rs0;
        l1 = l1 * corr1 + rs1;
        m0v = mn0;
        m1v = mn1;
#pragma unroll
        for (int nt = 0; nt < 8; nt++) {
            of[nt][0] *= corr0; of[nt][1] *= corr0;
            of[nt][2] *= corr1; of[nt][3] *= corr1;
        }
        __syncwarp();

        // O += P V
        {
            const uint32_t* Vu = (const uint32_t*)Vs;
#pragma unroll
            for (int kc = 0; kc < 8; kc++) {
                uint32_t af[4];
                const uint32_t* ab = Pu + r * 68 + kc * 8 + q;
                af[0] = ab[0];
                af[1] = ab[8 * 68];
                af[2] = ab[4];
                af[3] = ab[8 * 68 + 4];
#pragma unroll
                for (int nt = 0; nt < 8; nt++) {
                    uint32_t bf[2];
                    const uint32_t* bb = Vu + (kc * 8 + q) * 68 + nt * 8 + r;
                    bf[0] = bb[0];
                    bf[1] = bb[4 * 68];
                    mma_tf32(of[nt], af, bf);
                }
            }
        }
        __syncthreads();
    }

    // normalize + store
    const float inv0 = 1.0f / l0;
    const float inv1 = 1.0f / l1;
    const int row0 = q0 + wid * 16 + r;
#pragma unroll
    for (int nt = 0; nt < 8; nt++) {
        const int col = h * HD + nt * 8 + 2 * q;
        float2 w0 = {of[nt][0] * inv0, of[nt][1] * inv0};
        float2 w1 = {of[nt][2] * inv1, of[nt][3] * inv1};
        *(float2*)(out + (long)row0 * CDIM + col) = w0;
        *(float2*)(out + (long)(row0 + 8) * CDIM + col) = w1;
    }
}

// ---------------- launch -----------------------------------------------------
extern "C" void kernel_launch(void* const* d_in, const int* in_sizes, int n_in,
                              void* d_out, int out_size)
{
    const float* x      = (const float*)d_in[0];
    const float* cos_t  = (const float*)d_in[1];
    const float* sin_t  = (const float*)d_in[2];
    const float* w_qkv  = (const float*)d_in[3];
    const float* w_proj = (const float*)d_in[4];
    const float* b_proj = (const float*)d_in[5];
    const float* g1     = (const float*)d_in[6];
    const float* beta1  = (const float*)d_in[7];
    const float* g2     = (const float*)d_in[8];
    const float* beta2  = (const float*)d_in[9];
    const float* w_fc1  = (const float*)d_in[10];
    const float* b_fc1  = (const float*)d_in[11];
    const float* w_fc2  = (const float*)d_in[12];
    const float* b_fc2  = (const float*)d_in[13];
    float* out = (float*)d_out;

    float *h, *qkv, *o, *x1, *fc1;
    cudaGetSymbolAddress((void**)&h,   g_h);
    cudaGetSymbolAddress((void**)&qkv, g_qkv);
    cudaGetSymbolAddress((void**)&o,   g_o);
    cudaGetSymbolAddress((void**)&x1,  g_x1);
    cudaGetSymbolAddress((void**)&fc1, g_fc1);

    const int GEMM_SMEM = 2 * GSTAGE * 4;        // 73728
    const int ATTN_SMEM = (64 + 64 + 128) * 68 * 4;  // 69632
    cudaFuncSetAttribute(gemm_mma<false, false, false>,
                         cudaFuncAttributeMaxDynamicSharedMemorySize, GEMM_SMEM);
    cudaFuncSetAttribute(gemm_mma<true, true, false>,
                         cudaFuncAttributeMaxDynamicSharedMemorySize, GEMM_SMEM);
    cudaFuncSetAttribute(gemm_mma<true, false, true>,
                         cudaFuncAttributeMaxDynamicSharedMemorySize, GEMM_SMEM);
    cudaFuncSetAttribute(attn_mma,
                         cudaFuncAttributeMaxDynamicSharedMemorySize, ATTN_SMEM);

    // 1. h = LN1(x)
    ln_kernel<<<NTOK, 256>>>(x, g1, beta1, h);
    // 2. qkv = h @ w_qkv^T
    gemm_mma<false, false, false><<<dim3(QKVD / 128, NTOK / 128), 256, GEMM_SMEM>>>(
        h, w_qkv, nullptr, nullptr, qkv, NTOK, QKVD, CDIM);
    // 3. RoPE(q, k)
    rope_kernel<<<(NTOK * NH * 32 + 255) / 256, 256>>>(qkv, cos_t, sin_t);
    // 4. o = attention(q, k, v)
    attn_mma<<<dim3(NTOK / 128, NH), 256, ATTN_SMEM>>>(qkv, o);
    // 5. x1 = x + o @ w_proj^T + b_proj
    gemm_mma<true, true, false><<<dim3(CDIM / 128, NTOK / 128), 256, GEMM_SMEM>>>(
        o, w_proj, b_proj, x, x1, NTOK, CDIM, CDIM);
    // 6. h = LN2(x1)
    ln_kernel<<<NTOK, 256>>>(x1, g2, beta2, h);
    // 7. fc1 = gelu(h @ w_fc1^T + b_fc1)
    gemm_mma<true, false, true><<<dim3(FF / 128, NTOK / 128), 256, GEMM_SMEM>>>(
        h, w_fc1, b_fc1, nullptr, fc1, NTOK, FF, CDIM);
    // 8. out = x1 + fc1 @ w_fc2^T + b_fc2
    gemm_mma<true, true, false><<<dim3(CDIM / 128, NTOK / 128), 256, GEMM_SMEM>>>(
        fc1, w_fc2, b_fc2, x1, out, NTOK, CDIM, FF);
}